// round 5
// baseline (speedup 1.0000x reference)
#include <cuda_runtime.h>
#include <cuda_bf16.h>
#include <cstdint>

// Problem dims
#define B_  4
#define S_  2048
#define DM_ 2048
#define H_  16
#define HD_ 128
#define SCALE_ 0.08838834764831843f   // 1/sqrt(128)

typedef __nv_bfloat16 bf16;

// ---------------- scratch (__device__ globals: allocation-free rule) ----------------
__device__ bf16 g_xh[(size_t)B_ * S_ * DM_];      // 32 MB
__device__ bf16 g_xl[(size_t)B_ * S_ * DM_];
__device__ bf16 g_Qh[(size_t)B_ * S_ * DM_];
__device__ bf16 g_Ql[(size_t)B_ * S_ * DM_];
__device__ bf16 g_Kh[(size_t)B_ * S_ * HD_];
__device__ bf16 g_Kl[(size_t)B_ * S_ * HD_];
__device__ bf16 g_Vth[(size_t)B_ * HD_ * S_];     // [B][128][2048]
__device__ bf16 g_Vtl[(size_t)B_ * HD_ * S_];
__device__ bf16 g_attnh[(size_t)B_ * S_ * DM_];
__device__ bf16 g_attnl[(size_t)B_ * S_ * DM_];
__device__ bf16 g_Wqh[(size_t)DM_ * DM_];         // transposed [N][K]
__device__ bf16 g_Wql[(size_t)DM_ * DM_];
__device__ bf16 g_Wkh[(size_t)HD_ * DM_];
__device__ bf16 g_Wkl[(size_t)HD_ * DM_];
__device__ bf16 g_Wvh[(size_t)HD_ * DM_];
__device__ bf16 g_Wvl[(size_t)HD_ * DM_];
__device__ bf16 g_Woh[(size_t)DM_ * DM_];
__device__ bf16 g_Wol[(size_t)DM_ * DM_];
__device__ float g_rowsum[(size_t)B_ * H_ * S_];

// ---------------- smem layout ----------------
#define TILE_B     10240                 // 128 x 40 bf16
#define STAGE_BYTES (4 * TILE_B)         // Ah, Al, Bh, Bl
#define AUX_OFF    81920
#define RED_OFF    82432
#define SMEM_BYTES 83456
#define LDT 40

// ---------------- helpers ----------------
__device__ __forceinline__ uint32_t smem_u32(const void* p) {
    uint32_t a;
    asm("{ .reg .u64 t; cvta.to.shared.u64 t, %1; cvt.u32.u64 %0, t; }" : "=r"(a) : "l"(p));
    return a;
}
__device__ __forceinline__ void ldsm4(uint32_t* r, uint32_t a) {
    asm volatile("ldmatrix.sync.aligned.m8n8.x4.shared.b16 {%0,%1,%2,%3}, [%4];"
        : "=r"(r[0]), "=r"(r[1]), "=r"(r[2]), "=r"(r[3]) : "r"(a));
}
__device__ __forceinline__ void mma_bf16(float* d, const uint32_t* a, uint32_t b0, uint32_t b1) {
    asm volatile("mma.sync.aligned.m16n8k16.row.col.f32.bf16.bf16.f32 "
        "{%0,%1,%2,%3}, {%4,%5,%6,%7}, {%8,%9}, {%0,%1,%2,%3};"
        : "+f"(d[0]), "+f"(d[1]), "+f"(d[2]), "+f"(d[3])
        : "r"(a[0]), "r"(a[1]), "r"(a[2]), "r"(a[3]), "r"(b0), "r"(b1));
}
__device__ __forceinline__ uint32_t bits2(__nv_bfloat162 h) {
    return *reinterpret_cast<uint32_t*>(&h);
}
__device__ __forceinline__ void split4(float4 v, uint32_t& h0, uint32_t& h1,
                                       uint32_t& l0, uint32_t& l1) {
    __nv_bfloat162 a = __floats2bfloat162_rn(v.x, v.y);
    __nv_bfloat162 b = __floats2bfloat162_rn(v.z, v.w);
    float2 fa = __bfloat1622float2(a);
    float2 fb = __bfloat1622float2(b);
    __nv_bfloat162 c = __floats2bfloat162_rn(v.x - fa.x, v.y - fa.y);
    __nv_bfloat162 d = __floats2bfloat162_rn(v.z - fb.x, v.w - fb.y);
    h0 = bits2(a); h1 = bits2(b); l0 = bits2(c); l1 = bits2(d);
}

// MMA compute for one 32-wide K chunk (3-term split, frag reuse)
__device__ __forceinline__ void compute_chunk(float (*acc)[8][4], char* buf,
                                              int wm, int wn, int ar, int acsel) {
    bf16* Ah = (bf16*)(buf);
    bf16* Al = (bf16*)(buf + TILE_B);
    bf16* Bh = (bf16*)(buf + 2 * TILE_B);
    bf16* Bl = (bf16*)(buf + 3 * TILE_B);
#pragma unroll
    for (int kk = 0; kk < 32; kk += 16) {
        const int ac = kk + acsel;
        uint32_t aH[2][4], aL[2][4];
#pragma unroll
        for (int mt = 0; mt < 2; mt++) {
            ldsm4(aH[mt], smem_u32(Ah + (wm * 32 + mt * 16 + ar) * LDT + ac));
            ldsm4(aL[mt], smem_u32(Al + (wm * 32 + mt * 16 + ar) * LDT + ac));
        }
#pragma unroll
        for (int p = 0; p < 4; p++) {
            uint32_t bh[4], bl[4];
            ldsm4(bh, smem_u32(Bh + (wn * 64 + p * 16 + ar) * LDT + ac));
            ldsm4(bl, smem_u32(Bl + (wn * 64 + p * 16 + ar) * LDT + ac));
#pragma unroll
            for (int mt = 0; mt < 2; mt++) {
                mma_bf16(acc[mt][2 * p],     aH[mt], bh[0], bh[2]);
                mma_bf16(acc[mt][2 * p + 1], aH[mt], bh[1], bh[3]);
                mma_bf16(acc[mt][2 * p],     aH[mt], bl[0], bl[2]);
                mma_bf16(acc[mt][2 * p + 1], aH[mt], bl[1], bl[3]);
                mma_bf16(acc[mt][2 * p],     aL[mt], bh[0], bh[2]);
                mma_bf16(acc[mt][2 * p + 1], aL[mt], bh[1], bh[3]);
            }
        }
    }
}

// copy one pre-split 128x32 bf16 tile pair (hi+lo) gmem -> smem
__device__ __forceinline__ void copy_tile(const bf16* __restrict__ gh,
                                          const bf16* __restrict__ gl,
                                          size_t ld, int k0, bf16* sh, bf16* sl, int tid) {
#pragma unroll
    for (int i = 0; i < 2; i++) {
        int idx = i * 256 + tid;
        int r = idx >> 2, c = (idx & 3) << 3;
        uint4 vh = *(const uint4*)(gh + (size_t)r * ld + k0 + c);
        uint4 vl = *(const uint4*)(gl + (size_t)r * ld + k0 + c);
        int o = r * LDT + c;
        *(uint2*)(sh + o) = make_uint2(vh.x, vh.y);
        *(uint2*)(sh + o + 4) = make_uint2(vh.z, vh.w);
        *(uint2*)(sl + o) = make_uint2(vl.x, vl.y);
        *(uint2*)(sl + o + 4) = make_uint2(vl.z, vl.w);
    }
}

// core: acc = A[128,K] @ Bt[128,K]^T, all operands pre-split bf16
__device__ __forceinline__ void gemm_core_bf(
    float (*acc)[8][4],
    const bf16* __restrict__ Ahg, const bf16* __restrict__ Alg, size_t lda,
    const bf16* __restrict__ Bhg, const bf16* __restrict__ Blg, size_t ldb,
    int Kdim, char* smem)
{
    const int tid = threadIdx.x;
    const int wid = tid >> 5, lane = tid & 31;
    const int wm = wid & 3, wn = wid >> 2;
    const int ar = lane & 15;
    const int acsel = (lane >> 4) << 3;

#pragma unroll 1
    for (int k0 = 0; k0 < Kdim; k0 += 32) {
        char* buf = smem + (((k0 >> 5) & 1) ? STAGE_BYTES : 0);
        copy_tile(Ahg, Alg, lda, k0, (bf16*)buf, (bf16*)(buf + TILE_B), tid);
        copy_tile(Bhg, Blg, ldb, k0, (bf16*)(buf + 2 * TILE_B), (bf16*)(buf + 3 * TILE_B), tid);
        __syncthreads();
        compute_chunk(acc, buf, wm, wn, ar, acsel);
    }
    __syncthreads();
}

// PV core: A = fp32 scores (normalize by rinv, write back), B pre-split bf16
__device__ __forceinline__ void gemm_core_pv(
    float (*acc)[8][4], float* __restrict__ A, size_t lda,
    const bf16* __restrict__ Bhg, const bf16* __restrict__ Blg, size_t ldb,
    int Kdim, char* smem, const float* __restrict__ rinv)
{
    const int tid = threadIdx.x;
    const int wid = tid >> 5, lane = tid & 31;
    const int wm = wid & 3, wn = wid >> 2;
    const int ar = lane & 15;
    const int acsel = (lane >> 4) << 3;

#pragma unroll 1
    for (int k0 = 0; k0 < Kdim; k0 += 32) {
        char* buf = smem + (((k0 >> 5) & 1) ? STAGE_BYTES : 0);
        bf16* Ah = (bf16*)buf;
        bf16* Al = (bf16*)(buf + TILE_B);
#pragma unroll
        for (int i = 0; i < 4; i++) {
            int idx = i * 256 + tid;
            int r = idx >> 3, c = (idx & 7) << 2;
            float4 v = *(float4*)(A + (size_t)r * lda + k0 + c);
            float ri = rinv[r];
            v.x *= ri; v.y *= ri; v.z *= ri; v.w *= ri;
            *(float4*)(A + (size_t)r * lda + k0 + c) = v;
            uint32_t h0, h1, l0, l1; split4(v, h0, h1, l0, l1);
            int o = r * LDT + c;
            *(uint2*)(Ah + o) = make_uint2(h0, h1);
            *(uint2*)(Al + o) = make_uint2(l0, l1);
        }
        copy_tile(Bhg, Blg, ldb, k0, (bf16*)(buf + 2 * TILE_B), (bf16*)(buf + 3 * TILE_B), tid);
        __syncthreads();
        compute_chunk(acc, buf, wm, wn, ar, acsel);
    }
    __syncthreads();
}

// stage acc (fp32) into smem [128][132]
__device__ __forceinline__ void stage_acc(float (*acc)[8][4], float* stg, int wid, int lane) {
    int wm = wid & 3, wn = wid >> 2;
    int r0 = wm * 32 + (lane >> 2), c0 = wn * 64 + (lane & 3) * 2;
#pragma unroll
    for (int mt = 0; mt < 2; mt++)
#pragma unroll
        for (int nt = 0; nt < 8; nt++) {
            int r = r0 + mt * 16, c = c0 + nt * 8;
            *(float2*)&stg[r * 132 + c] = make_float2(acc[mt][nt][0], acc[mt][nt][1]);
            *(float2*)&stg[(r + 8) * 132 + c] = make_float2(acc[mt][nt][2], acc[mt][nt][3]);
        }
}

#define ZERO_ACC(acc) \
    _Pragma("unroll") for (int i = 0; i < 2; i++) \
    _Pragma("unroll") for (int j = 0; j < 8; j++) \
    _Pragma("unroll") for (int q = 0; q < 4; q++) acc[i][j][q] = 0.0f;

// ---------------- prep kernels ----------------
__global__ void split_x_kernel(const float* __restrict__ x, bf16* __restrict__ xh,
                               bf16* __restrict__ xl, int n4) {
    int i = blockIdx.x * blockDim.x + threadIdx.x;
    if (i >= n4) return;
    float4 v = *(const float4*)(x + 4 * (size_t)i);
    uint32_t h0, h1, l0, l1; split4(v, h0, h1, l0, l1);
    *(uint2*)(xh + 4 * (size_t)i) = make_uint2(h0, h1);
    *(uint2*)(xl + 4 * (size_t)i) = make_uint2(l0, l1);
}

// dst[N][M] (split) = src[M][N]
__global__ void transpose_split_kernel(const float* __restrict__ src,
                                       bf16* __restrict__ dh, bf16* __restrict__ dl,
                                       int M, int N) {
    __shared__ float t[32][33];
    int bx = blockIdx.x * 32, by = blockIdx.y * 32;
    int x = threadIdx.x, y0 = threadIdx.y;
#pragma unroll
    for (int j = 0; j < 32; j += 8)
        t[y0 + j][x] = src[(size_t)(by + y0 + j) * N + bx + x];
    __syncthreads();
#pragma unroll
    for (int j = 0; j < 32; j += 8) {
        float v = t[x][y0 + j];
        bf16 h = __float2bfloat16_rn(v);
        bf16 l = __float2bfloat16_rn(v - __bfloat162float(h));
        size_t o = (size_t)(bx + y0 + j) * M + by + x;
        dh[o] = h; dl[o] = l;
    }
}
__global__ void zero_kernel(float* p, int n) {
    int i = blockIdx.x * blockDim.x + threadIdx.x;
    if (i < n) p[i] = 0.0f;
}

// ---------------- proj GEMM with split epilogue: Ch/Cl = split(A@Bt^T + bias) ----------------
__global__ __launch_bounds__(256, 2) void mma_proj_split(
    const bf16* __restrict__ Ahg, const bf16* __restrict__ Alg, size_t lda,
    const bf16* __restrict__ Bhg, const bf16* __restrict__ Blg, size_t ldb,
    const float* __restrict__ bias,
    bf16* __restrict__ Ch, bf16* __restrict__ Cl, size_t ldc, int Kdim)
{
    extern __shared__ __align__(16) char smem[];
    const int tid = threadIdx.x, wid = tid >> 5, lane = tid & 31;
    const int row0 = blockIdx.y * 128, col0 = blockIdx.x * 128;

    float* bs = (float*)(smem + AUX_OFF);
    if (tid < 128) bs[tid] = bias[col0 + tid];

    float acc[2][8][4];
    ZERO_ACC(acc)
    gemm_core_bf(acc, Ahg + (size_t)row0 * lda, Alg + (size_t)row0 * lda, lda,
                 Bhg + (size_t)col0 * ldb, Blg + (size_t)col0 * ldb, ldb, Kdim, smem);

    float* stg = (float*)smem;
    stage_acc(acc, stg, wid, lane);
    __syncthreads();
#pragma unroll 1
    for (int i = 0; i < 16; i++) {
        int idx = i * 256 + tid;
        int rr = idx >> 5, c4 = (idx & 31) << 2;
        float4 v = *(float4*)&stg[rr * 132 + c4];
        v.x += bs[c4]; v.y += bs[c4 + 1]; v.z += bs[c4 + 2]; v.w += bs[c4 + 3];
        uint32_t h0, h1, l0, l1; split4(v, h0, h1, l0, l1);
        size_t o = (size_t)(row0 + rr) * ldc + col0 + c4;
        *(uint2*)(Ch + o) = make_uint2(h0, h1);
        *(uint2*)(Cl + o) = make_uint2(l0, l1);
    }
}

// ---------------- V projection with transposed split epilogue ----------------
__global__ __launch_bounds__(256, 2) void mma_vproj(
    const bf16* __restrict__ Ahg, const bf16* __restrict__ Alg,
    const bf16* __restrict__ Bhg, const bf16* __restrict__ Blg,
    const float* __restrict__ bias, bf16* __restrict__ Vth, bf16* __restrict__ Vtl)
{
    extern __shared__ __align__(16) char smem[];
    const int tid = threadIdx.x, wid = tid >> 5, lane = tid & 31;
    const int row0 = blockIdx.y * 128;

    float* bs = (float*)(smem + AUX_OFF);
    if (tid < 128) bs[tid] = bias[tid];

    float acc[2][8][4];
    ZERO_ACC(acc)
    gemm_core_bf(acc, Ahg + (size_t)row0 * DM_, Alg + (size_t)row0 * DM_, DM_,
                 Bhg, Blg, DM_, DM_, smem);

    float* stg = (float*)smem;
    stage_acc(acc, stg, wid, lane);
    __syncthreads();
    int b = row0 >> 11;
    int s0 = row0 & (S_ - 1);
    bf16* Vbh = Vth + (size_t)b * HD_ * S_;
    bf16* Vbl = Vtl + (size_t)b * HD_ * S_;
#pragma unroll 1
    for (int i = 0; i < 64; i++) {
        int idx = i * 256 + tid;
        int m = idx & 127, n = idx >> 7;
        float v = stg[m * 132 + n] + bs[n];
        bf16 h = __float2bfloat16_rn(v);
        bf16 l = __float2bfloat16_rn(v - __bfloat162float(h));
        Vbh[(size_t)n * S_ + s0 + m] = h;
        Vbl[(size_t)n * S_ + s0 + m] = l;
    }
}

// ---------------- scores: E = exp(scale * Q Kt) + rowsums ----------------
__global__ __launch_bounds__(256, 2) void mma_scores(
    const bf16* __restrict__ Qh, const bf16* __restrict__ Ql,
    const bf16* __restrict__ Kh, const bf16* __restrict__ Kl,
    float* __restrict__ scores, float* __restrict__ rowsum)
{
    extern __shared__ __align__(16) char smem[];
    const int tid = threadIdx.x, wid = tid >> 5, lane = tid & 31;
    const int bh = blockIdx.z;
    const int b = bh >> 4, h = bh & 15;
    const int row0 = blockIdx.y * 128, col0 = blockIdx.x * 128;

    float acc[2][8][4];
    ZERO_ACC(acc)
    gemm_core_bf(acc,
        Qh + ((size_t)b * S_ + row0) * DM_ + h * HD_,
        Ql + ((size_t)b * S_ + row0) * DM_ + h * HD_, DM_,
        Kh + ((size_t)b * S_ + col0) * HD_,
        Kl + ((size_t)b * S_ + col0) * HD_, HD_, HD_, smem);

    float* stg = (float*)smem;
    float* red = (float*)(smem + RED_OFF);
    const int wm = wid & 3, wn = wid >> 2;
    const int r0 = wm * 32 + (lane >> 2), c0 = wn * 64 + (lane & 3) * 2;
    float sums[2][2] = {{0.f, 0.f}, {0.f, 0.f}};
#pragma unroll
    for (int mt = 0; mt < 2; mt++)
#pragma unroll
        for (int nt = 0; nt < 8; nt++) {
            float e0 = __expf(acc[mt][nt][0] * SCALE_);
            float e1 = __expf(acc[mt][nt][1] * SCALE_);
            float e2 = __expf(acc[mt][nt][2] * SCALE_);
            float e3 = __expf(acc[mt][nt][3] * SCALE_);
            int r = r0 + mt * 16, c = c0 + nt * 8;
            *(float2*)&stg[r * 132 + c] = make_float2(e0, e1);
            *(float2*)&stg[(r + 8) * 132 + c] = make_float2(e2, e3);
            sums[mt][0] += e0 + e1;
            sums[mt][1] += e2 + e3;
        }
#pragma unroll
    for (int mt = 0; mt < 2; mt++)
#pragma unroll
        for (int hh = 0; hh < 2; hh++) {
            float v = sums[mt][hh];
            v += __shfl_xor_sync(0xFFFFFFFFu, v, 1);
            v += __shfl_xor_sync(0xFFFFFFFFu, v, 2);
            sums[mt][hh] = v;
        }
    if ((lane & 3) == 0) {
#pragma unroll
        for (int mt = 0; mt < 2; mt++)
#pragma unroll
            for (int hh = 0; hh < 2; hh++)
                red[(wm * 32 + mt * 16 + hh * 8 + (lane >> 2)) * 2 + wn] = sums[mt][hh];
    }
    __syncthreads();
    if (tid < 128)
        atomicAdd(&rowsum[(size_t)bh * S_ + row0 + tid], red[tid * 2] + red[tid * 2 + 1]);

    float* Crow = scores + ((size_t)bh * S_ + row0) * S_ + col0;
#pragma unroll 1
    for (int i = 0; i < 16; i++) {
        int idx = i * 256 + tid;
        int rr = idx >> 5, c4 = (idx & 31) << 2;
        *(float4*)&Crow[(size_t)rr * S_ + c4] = *(float4*)&stg[rr * 132 + c4];
    }
}

// ---------------- normalize scores in place + PV (split epilogue) ----------------
__global__ __launch_bounds__(256, 2) void mma_softmax_pv(
    float* __restrict__ scores, const float* __restrict__ rowsum,
    const bf16* __restrict__ Vth, const bf16* __restrict__ Vtl,
    bf16* __restrict__ attnh, bf16* __restrict__ attnl)
{
    extern __shared__ __align__(16) char smem[];
    const int tid = threadIdx.x, wid = tid >> 5, lane = tid & 31;
    const int bh = blockIdx.y;
    const int b = bh >> 4, h = bh & 15;
    const int row0 = blockIdx.x * 128;

    float* rinv = (float*)(smem + AUX_OFF);
    if (tid < 128) rinv[tid] = 1.0f / rowsum[(size_t)bh * S_ + row0 + tid];
    __syncthreads();

    float acc[2][8][4];
    ZERO_ACC(acc)
    gemm_core_pv(acc, scores + ((size_t)bh * S_ + row0) * S_, S_,
                 Vth + (size_t)b * HD_ * S_, Vtl + (size_t)b * HD_ * S_, S_,
                 S_, smem, rinv);

    float* stg = (float*)smem;
    stage_acc(acc, stg, wid, lane);
    __syncthreads();
    bf16* Cbh = attnh + ((size_t)b * S_ + row0) * DM_ + h * HD_;
    bf16* Cbl = attnl + ((size_t)b * S_ + row0) * DM_ + h * HD_;
#pragma unroll 1
    for (int i = 0; i < 16; i++) {
        int idx = i * 256 + tid;
        int rr = idx >> 5, c4 = (idx & 31) << 2;
        float4 v = *(float4*)&stg[rr * 132 + c4];
        uint32_t h0, h1, l0, l1; split4(v, h0, h1, l0, l1);
        size_t o = (size_t)rr * DM_ + c4;
        *(uint2*)(Cbh + o) = make_uint2(h0, h1);
        *(uint2*)(Cbl + o) = make_uint2(l0, l1);
    }
}

// ---------------- output GEMM (fp32 + bias epilogue) ----------------
__global__ __launch_bounds__(256, 2) void mma_out(
    const bf16* __restrict__ Ahg, const bf16* __restrict__ Alg,
    const bf16* __restrict__ Bhg, const bf16* __restrict__ Blg,
    const float* __restrict__ bias, float* __restrict__ C)
{
    extern __shared__ __align__(16) char smem[];
    const int tid = threadIdx.x, wid = tid >> 5, lane = tid & 31;
    const int row0 = blockIdx.y * 128, col0 = blockIdx.x * 128;

    float* bs = (float*)(smem + AUX_OFF);
    if (tid < 128) bs[tid] = bias[col0 + tid];

    float acc[2][8][4];
    ZERO_ACC(acc)
    gemm_core_bf(acc, Ahg + (size_t)row0 * DM_, Alg + (size_t)row0 * DM_, DM_,
                 Bhg + (size_t)col0 * DM_, Blg + (size_t)col0 * DM_, DM_, DM_, smem);

    float* stg = (float*)smem;
    stage_acc(acc, stg, wid, lane);
    __syncthreads();
#pragma unroll 1
    for (int i = 0; i < 16; i++) {
        int idx = i * 256 + tid;
        int rr = idx >> 5, c4 = (idx & 31) << 2;
        float4 v = *(float4*)&stg[rr * 132 + c4];
        v.x += bs[c4]; v.y += bs[c4 + 1]; v.z += bs[c4 + 2]; v.w += bs[c4 + 3];
        *(float4*)&C[(size_t)(row0 + rr) * DM_ + col0 + c4] = v;
    }
}

// ---------------- launch ----------------
extern "C" void kernel_launch(void* const* d_in, const int* in_sizes, int n_in,
                              void* d_out, int out_size)
{
    const float* x  = (const float*)d_in[0];
    const float* Wq = (const float*)d_in[1];
    const float* bq = (const float*)d_in[2];
    const float* Wk = (const float*)d_in[3];
    const float* bk = (const float*)d_in[4];
    const float* Wv = (const float*)d_in[5];
    const float* bv = (const float*)d_in[6];
    const float* Wo = (const float*)d_in[7];
    const float* bo = (const float*)d_in[8];

    float* out = (float*)d_out;
    float* scores = out + (size_t)B_ * S_ * DM_;

    bf16 *pxh, *pxl, *pQh, *pQl, *pKh, *pKl, *pVth, *pVtl, *pAh, *pAl;
    bf16 *pWqh, *pWql, *pWkh, *pWkl, *pWvh, *pWvl, *pWoh, *pWol;
    float* pRS;
    cudaGetSymbolAddress((void**)&pxh, g_xh);   cudaGetSymbolAddress((void**)&pxl, g_xl);
    cudaGetSymbolAddress((void**)&pQh, g_Qh);   cudaGetSymbolAddress((void**)&pQl, g_Ql);
    cudaGetSymbolAddress((void**)&pKh, g_Kh);   cudaGetSymbolAddress((void**)&pKl, g_Kl);
    cudaGetSymbolAddress((void**)&pVth, g_Vth); cudaGetSymbolAddress((void**)&pVtl, g_Vtl);
    cudaGetSymbolAddress((void**)&pAh, g_attnh); cudaGetSymbolAddress((void**)&pAl, g_attnl);
    cudaGetSymbolAddress((void**)&pWqh, g_Wqh); cudaGetSymbolAddress((void**)&pWql, g_Wql);
    cudaGetSymbolAddress((void**)&pWkh, g_Wkh); cudaGetSymbolAddress((void**)&pWkl, g_Wkl);
    cudaGetSymbolAddress((void**)&pWvh, g_Wvh); cudaGetSymbolAddress((void**)&pWvl, g_Wvl);
    cudaGetSymbolAddress((void**)&pWoh, g_Woh); cudaGetSymbolAddress((void**)&pWol, g_Wol);
    cudaGetSymbolAddress((void**)&pRS, g_rowsum);

    static int smem_set = 0;
    if (!smem_set) {
        cudaFuncSetAttribute(mma_proj_split, cudaFuncAttributeMaxDynamicSharedMemorySize, SMEM_BYTES);
        cudaFuncSetAttribute(mma_vproj, cudaFuncAttributeMaxDynamicSharedMemorySize, SMEM_BYTES);
        cudaFuncSetAttribute(mma_scores, cudaFuncAttributeMaxDynamicSharedMemorySize, SMEM_BYTES);
        cudaFuncSetAttribute(mma_softmax_pv, cudaFuncAttributeMaxDynamicSharedMemorySize, SMEM_BYTES);
        cudaFuncSetAttribute(mma_out, cudaFuncAttributeMaxDynamicSharedMemorySize, SMEM_BYTES);
        smem_set = 1;
    }

    const int M = B_ * S_;   // 8192
    split_x_kernel<<<(M * DM_ / 4 + 255) / 256, 256>>>(x, pxh, pxl, M * DM_ / 4);
    transpose_split_kernel<<<dim3(DM_ / 32, DM_ / 32), dim3(32, 8)>>>(Wq, pWqh, pWql, DM_, DM_);
    transpose_split_kernel<<<dim3(HD_ / 32, DM_ / 32), dim3(32, 8)>>>(Wk, pWkh, pWkl, DM_, HD_);
    transpose_split_kernel<<<dim3(HD_ / 32, DM_ / 32), dim3(32, 8)>>>(Wv, pWvh, pWvl, DM_, HD_);
    transpose_split_kernel<<<dim3(DM_ / 32, DM_ / 32), dim3(32, 8)>>>(Wo, pWoh, pWol, DM_, DM_);
    zero_kernel<<<(B_ * H_ * S_ + 255) / 256, 256>>>(pRS, B_ * H_ * S_);

    mma_proj_split<<<dim3(DM_ / 128, M / 128), 256, SMEM_BYTES>>>(
        pxh, pxl, DM_, pWqh, pWql, DM_, bq, pQh, pQl, DM_, DM_);
    mma_proj_split<<<dim3(1, M / 128), 256, SMEM_BYTES>>>(
        pxh, pxl, DM_, pWkh, pWkl, DM_, bk, pKh, pKl, HD_, DM_);
    mma_vproj<<<dim3(1, M / 128), 256, SMEM_BYTES>>>(
        pxh, pxl, pWvh, pWvl, bv, pVth, pVtl);

    mma_scores<<<dim3(S_ / 128, S_ / 128, B_ * H_), 256, SMEM_BYTES>>>(
        pQh, pQl, pKh, pKl, scores, pRS);
    mma_softmax_pv<<<dim3(S_ / 128, B_ * H_), 256, SMEM_BYTES>>>(
        scores, pRS, pVth, pVtl, pAh, pAl);

    mma_out<<<dim3(DM_ / 128, M / 128), 256, SMEM_BYTES>>>(
        pAh, pAl, pWoh, pWol, bo, out);
}